// round 9
// baseline (speedup 1.0000x reference)
#include <cuda_runtime.h>
#include <math.h>

#define WIDTH  128
#define HEIGHT 128
#define NEARP  0.1f
#define FARP   10.0f
#define EPSV   1e-8f

#define THREADS   1024
#define PX_BLK    128    // one full image row per block
#define SLICES    32     // warps per block
#define PPT       4      // pixels per thread (lane, +32, +64, +96)

__device__ __forceinline__ void compute_mvp(const float* cf, const float* cc,
                                            const float* tt, const float* rt,
                                            float* MVP) {
    float r0 = rt[0], r1 = rt[1], r2 = rt[2];
    float theta = sqrtf(r0 * r0 + r1 * r1 + r2 * r2 + 1e-12f);
    float k0 = r0 / theta, k1 = r1 / theta, k2 = r2 / theta;
    float st = sinf(theta), ctv = cosf(theta);
    float K[9] = { 0.f, -k2,  k1,
                   k2,  0.f, -k0,
                  -k1,  k0,  0.f };
    float KK[9];
    for (int i = 0; i < 3; i++)
        for (int j = 0; j < 3; j++) {
            float s = 0.f;
            for (int k = 0; k < 3; k++) s += K[i * 3 + k] * K[k * 3 + j];
            KK[i * 3 + j] = s;
        }
    float R[9];
    for (int i = 0; i < 3; i++)
        for (int j = 0; j < 3; j++)
            R[i * 3 + j] = (i == j ? 1.f : 0.f) + st * K[i * 3 + j] + (1.f - ctv) * KK[i * 3 + j];

    float Vw[16];
    for (int i = 0; i < 3; i++) {
        for (int j = 0; j < 3; j++) Vw[i * 4 + j] = R[j * 3 + i];
        Vw[i * 4 + 3] = 0.f;
    }
    Vw[12] = tt[0]; Vw[13] = tt[1]; Vw[14] = tt[2]; Vw[15] = 1.f;

    float fav = 0.5f * (cf[0] + cf[1]);
    float s = NEARP / fav;
    float right  = ((float)WIDTH - (cc[0] + 0.5f)) * s;
    float left   = -(cc[0] + 0.5f) * s;
    float top    = (cc[1] + 0.5f) * s;
    float bottom = -((float)HEIGHT - cc[1] + 0.5f) * s;
    float P[16];
    for (int i = 0; i < 16; i++) P[i] = 0.f;
    P[0]  = 2.f * NEARP / (right - left);
    P[5]  = 2.f * NEARP / (top - bottom);
    P[8]  = (right + left) / (right - left);
    P[9]  = (top + bottom) / (top - bottom);
    P[10] = -(FARP + NEARP) / (FARP - NEARP);
    P[11] = -1.f;
    P[14] = -2.f * FARP * NEARP / (FARP - NEARP);

    for (int i = 0; i < 4; i++)
        for (int j = 0; j < 4; j++) {
            float sij = 0.f;
            for (int k = 0; k < 4; k++) sij += Vw[i * 4 + k] * P[k * 4 + j];
            MVP[i * 4 + j] = sij;
        }
}

// One block (1024 thr) per image row. setup -> quantized-bbox compaction ->
// balanced eval (warp=slice, 4 px/thread) -> shared atomicMin (z,idx) argmin
// -> shade. Survivor eval arithmetic is bit-identical to the reference.
extern "C" __global__ void __launch_bounds__(THREADS, 1)
render_kernel(const float* __restrict__ v,
              const float* __restrict__ vc,
              const int*   __restrict__ f,
              const float* __restrict__ bg,
              const float* __restrict__ cf,
              const float* __restrict__ cc,
              const float* __restrict__ ct,
              const float* __restrict__ crt,
              float* __restrict__ out,
              int Vn, int Fn) {
    extern __shared__ char smem_raw[];
    float4*   s_triA = (float4*)smem_raw;                             // Fn
    float4*   s_triB = (float4*)((char*)s_triA + (size_t)Fn * 16);    // Fn
    float2*   s_triC = (float2*)((char*)s_triB + (size_t)Fn * 16);    // Fn
    unsigned* s_bbq  = (unsigned*)((char*)s_triC + (size_t)Fn * 8);   // Fn
    float4*   s_vert = (float4*)((char*)s_bbq + (size_t)Fn * 4);      // Vn
    unsigned long long* s_red =
        (unsigned long long*)((char*)s_vert + (size_t)Vn * 16);       // PX_BLK
    int* s_list = (int*)((char*)s_red + (size_t)PX_BLK * 8);          // Fn
    __shared__ float MVP[16];
    __shared__ int s_cnt;

    int tid = threadIdx.x;
    int b   = blockIdx.y;

    if (tid == 0) { compute_mvp(cf, cc, ct, crt, MVP); s_cnt = 0; }
    if (tid < PX_BLK) s_red[tid] = ~0ull;
    __syncthreads();

    // ---- vertex transform (validity folded into sign of .w) ----
    for (int i = tid; i < Vn; i += THREADS) {
        const float* vp = v + ((size_t)b * Vn + i) * 3;
        float X = vp[0], Y = vp[1], Z = vp[2];
        float c0 = X * MVP[0] + Y * MVP[4] + Z * MVP[8]  + MVP[12];
        float c1 = X * MVP[1] + Y * MVP[5] + Z * MVP[9]  + MVP[13];
        float c2 = X * MVP[2] + Y * MVP[6] + Z * MVP[10] + MVP[14];
        float c3 = X * MVP[3] + Y * MVP[7] + Z * MVP[11] + MVP[15];
        bool valid = c3 > EPSV;
        float ws = valid ? c3 : 1.f;
        float nx = c0 / ws, ny = c1 / ws, nz = c2 / ws;
        float xs = (nx * 0.5f + 0.5f) * (float)WIDTH;
        float ys = (0.5f - ny * 0.5f) * (float)HEIGHT;
        float iw = 1.f / ws;
        s_vert[i] = make_float4(xs, ys, nz, valid ? iw : -1.f);
    }
    __syncthreads();

    // ---- triangle setup + conservative quantized bbox ----
    for (int t = tid; t < Fn; t += THREADS) {
        int i0 = f[t * 3 + 0], i1 = f[t * 3 + 1], i2 = f[t * 3 + 2];
        float4 A  = s_vert[i0];
        float4 Bv = s_vert[i1];
        float4 C  = s_vert[i2];
        float area = (Bv.x - A.x) * (C.y - A.y) - (Bv.y - A.y) * (C.x - A.x);
        bool va = fabsf(area) > EPSV;
        float area_safe = va ? area : 1.f;
        float inva = 1.f / area_safe;
        bool valid = (A.w > 0.f) && (Bv.w > 0.f) && (C.w > 0.f) && va;
        float za = A.z, zb = Bv.z, zc = C.z;
        if (!valid) {
            float qn = __int_as_float(0x7FC00000);   // NaN -> never selected
            za = qn; zb = qn; zc = qn;
        }
        int xmn = __float2int_rd(fminf(A.x, fminf(Bv.x, C.x)));
        int xmx = __float2int_ru(fmaxf(A.x, fmaxf(Bv.x, C.x)));
        int ymn = __float2int_rd(fminf(A.y, fminf(Bv.y, C.y)));
        int ymx = __float2int_ru(fmaxf(A.y, fmaxf(Bv.y, C.y)));
        xmn = min(max(xmn, 0), 255); xmx = min(max(xmx, 0), 255);
        ymn = min(max(ymn, 0), 255); ymx = min(max(ymx, 0), 255);
        s_bbq[t]  = (unsigned)xmn | ((unsigned)xmx << 8) |
                    ((unsigned)ymn << 16) | ((unsigned)ymx << 24);
        s_triA[t] = make_float4(A.x, A.y, Bv.x, Bv.y);
        s_triB[t] = make_float4(C.x, C.y, za, zb);
        s_triC[t] = make_float2(zc, inva);
    }
    __syncthreads();

    // ---- bbox compaction for this row ----
    int row = blockIdx.x;
    float y = (float)row + 0.5f;

    for (int t = tid; t < Fn; t += THREADS) {
        unsigned q = s_bbq[t];
        int xmn = q & 255;
        int ymn = (q >> 16) & 255, ymx = q >> 24;
        bool hit = (ymn <= row) && (ymx > row) && (xmn <= WIDTH - 1);
        if (hit) {
            int slot = atomicAdd(&s_cnt, 1);   // unordered ok: key-min is order-invariant
            s_list[slot] = t;
        }
    }
    __syncthreads();
    int n = s_cnt;

    // ---- balanced eval: warp = slice, thread = 4 pixels ----
    int lane  = tid & 31;
    int slice = tid >> 5;
    float x0 = (float)lane + 0.5f;

    float bz[PPT];
    int   bi[PPT];
#pragma unroll
    for (int j = 0; j < PPT; j++) { bz[j] = INFINITY; bi[j] = -1; }

    for (int i = slice; i < n; i += SLICES) {
        int t = s_list[i];                // warp-uniform broadcast
        float4 TA = s_triA[t];            // Ax,Ay,Bx,By
        float4 TB = s_triB[t];            // Cx,Cy,za,zb
        float2 TC = s_triC[t];            // zc,inva
        float dCBx = TB.x - TA.z, dCBy = TB.y - TA.w;
        float dACx = TA.x - TB.x, dACy = TA.y - TB.y;
        float dBAx = TA.z - TA.x, dBAy = TA.w - TA.y;
        float ymB = y - TA.w, ymC = y - TB.y, ymA = y - TA.y;
        float inva = TC.y;

#pragma unroll
        for (int j = 0; j < PPT; j++) {
            float x = x0 + (float)(j * 32);
            float w0 = dCBx * ymB - dCBy * (x - TA.z);
            float w1 = dACx * ymC - dACy * (x - TB.x);
            float w2 = dBAx * ymA - dBAy * (x - TA.x);
            float b0 = w0 * inva, b1 = w1 * inva, b2 = w2 * inva;
            float z = b0 * TB.z + b1 * TB.w + b2 * TC.x;   // NaN if invalid
            bool inside = (b0 >= 0.f) && (b1 >= 0.f) && (b2 >= 0.f) &&
                          (z >= -1.f) && (z <= 1.f);
            if (inside && z < bz[j]) { bz[j] = z; bi[j] = t; }
        }
    }

    // per-pixel argmin via shared 64-bit atomicMin on packed (z,idx) keys
#pragma unroll
    for (int j = 0; j < PPT; j++) {
        if (bi[j] >= 0) {
            unsigned zu = __float_as_uint(bz[j]);
            zu = (zu & 0x80000000u) ? ~zu : (zu | 0x80000000u);
            unsigned long long key =
                ((unsigned long long)zu << 32) | (unsigned)bi[j];
            atomicMin(&s_red[lane + j * 32], key);
        }
    }
    __syncthreads();

    // ---- shade (first PX_BLK threads) ----
    if (tid < PX_BLK) {
        int p = tid;
        unsigned long long best = s_red[p];
        float xp = (float)p + 0.5f;
        float cr, cg, cb;
        if ((unsigned)(best >> 32) == 0xFFFFFFFFu) {
            cr = bg[0]; cg = bg[1]; cb = bg[2];
        } else {
            int tt = (int)(unsigned)best;
            float4 A4 = s_triA[tt];
            float4 B4 = s_triB[tt];
            float2 C2 = s_triC[tt];
            float dCBx = B4.x - A4.z, dCBy = B4.y - A4.w;
            float dACx = A4.x - B4.x, dACy = A4.y - B4.y;
            float dBAx = A4.z - A4.x, dBAy = A4.w - A4.y;
            float w0 = dCBx * (y - A4.w) - dCBy * (xp - A4.z);
            float w1 = dACx * (y - B4.y) - dACy * (xp - B4.x);
            float w2 = dBAx * (y - A4.y) - dBAy * (xp - A4.x);
            float inva = C2.y;
            float b0 = w0 * inva, b1 = w1 * inva, b2 = w2 * inva;
            int i0 = f[tt * 3 + 0], i1 = f[tt * 3 + 1], i2 = f[tt * 3 + 2];
            float q0 = b0 * s_vert[i0].w;   // selected => all verts valid => +invw
            float q1 = b1 * s_vert[i1].w;
            float q2 = b2 * s_vert[i2].w;
            float den = q0 + q1 + q2;
            if (!(fabsf(den) > EPSV)) den = 1.f;
            cr = (q0 * vc[i0 * 3 + 0] + q1 * vc[i1 * 3 + 0] + q2 * vc[i2 * 3 + 0]) / den;
            cg = (q0 * vc[i0 * 3 + 1] + q1 * vc[i1 * 3 + 1] + q2 * vc[i2 * 3 + 1]) / den;
            cb = (q0 * vc[i0 * 3 + 2] + q1 * vc[i1 * 3 + 2] + q2 * vc[i2 * 3 + 2]) / den;
        }
        float* op = out + ((size_t)b * HEIGHT * WIDTH + (size_t)row * WIDTH + p) * 3;
        op[0] = cr; op[1] = cg; op[2] = cb;
    }
}

extern "C" void kernel_launch(void* const* d_in, const int* in_sizes, int n_in,
                              void* d_out, int out_size) {
    const float* v   = (const float*)d_in[0];
    const float* vc  = (const float*)d_in[1];
    const int*   f   = (const int*)d_in[2];
    const float* bg  = (const float*)d_in[3];
    const float* cf  = (const float*)d_in[4];
    const float* cc  = (const float*)d_in[5];
    const float* ct  = (const float*)d_in[6];
    const float* crt = (const float*)d_in[7];

    int Vn = in_sizes[1] / 3;
    int Fn = in_sizes[2] / 3;
    int Bn = in_sizes[0] / (3 * Vn);

    size_t smem = (size_t)Fn * 44 + (size_t)Vn * 16 +
                  (size_t)PX_BLK * 8 + (size_t)Fn * 4;
    static int smem_set = 0;
    if (!smem_set) {
        cudaFuncSetAttribute(render_kernel,
                             cudaFuncAttributeMaxDynamicSharedMemorySize,
                             (int)smem);
        smem_set = 1;
    }
    dim3 grid(HEIGHT, Bn);
    render_kernel<<<grid, THREADS, smem>>>(v, vc, f, bg, cf, cc, ct, crt,
                                           (float*)d_out, Vn, Fn);
}

// round 11
// speedup vs baseline: 1.1501x; 1.1501x over previous
#include <cuda_runtime.h>
#include <math.h>

#define WIDTH  128
#define HEIGHT 128
#define NPX    (WIDTH * HEIGHT)
#define NEARP  0.1f
#define FARP   10.0f
#define EPSV   1e-8f

#define THREADS   512
#define GRIDX     296    // 2 * 148 SMs: exactly 2 blocks per SM
#define SLICES    16     // warps per block
#define MAXPXB    64     // max pixels per block (ceil(16384/296)=56 <= 64)

__device__ __forceinline__ void compute_mvp(const float* cf, const float* cc,
                                            const float* tt, const float* rt,
                                            float* MVP) {
    float r0 = rt[0], r1 = rt[1], r2 = rt[2];
    float theta = sqrtf(r0 * r0 + r1 * r1 + r2 * r2 + 1e-12f);
    float k0 = r0 / theta, k1 = r1 / theta, k2 = r2 / theta;
    float st = sinf(theta), ctv = cosf(theta);
    float K[9] = { 0.f, -k2,  k1,
                   k2,  0.f, -k0,
                  -k1,  k0,  0.f };
    float KK[9];
    for (int i = 0; i < 3; i++)
        for (int j = 0; j < 3; j++) {
            float s = 0.f;
            for (int k = 0; k < 3; k++) s += K[i * 3 + k] * K[k * 3 + j];
            KK[i * 3 + j] = s;
        }
    float R[9];
    for (int i = 0; i < 3; i++)
        for (int j = 0; j < 3; j++)
            R[i * 3 + j] = (i == j ? 1.f : 0.f) + st * K[i * 3 + j] + (1.f - ctv) * KK[i * 3 + j];

    float Vw[16];
    for (int i = 0; i < 3; i++) {
        for (int j = 0; j < 3; j++) Vw[i * 4 + j] = R[j * 3 + i];
        Vw[i * 4 + 3] = 0.f;
    }
    Vw[12] = tt[0]; Vw[13] = tt[1]; Vw[14] = tt[2]; Vw[15] = 1.f;

    float fav = 0.5f * (cf[0] + cf[1]);
    float s = NEARP / fav;
    float right  = ((float)WIDTH - (cc[0] + 0.5f)) * s;
    float left   = -(cc[0] + 0.5f) * s;
    float top    = (cc[1] + 0.5f) * s;
    float bottom = -((float)HEIGHT - cc[1] + 0.5f) * s;
    float P[16];
    for (int i = 0; i < 16; i++) P[i] = 0.f;
    P[0]  = 2.f * NEARP / (right - left);
    P[5]  = 2.f * NEARP / (top - bottom);
    P[8]  = (right + left) / (right - left);
    P[9]  = (top + bottom) / (top - bottom);
    P[10] = -(FARP + NEARP) / (FARP - NEARP);
    P[11] = -1.f;
    P[14] = -2.f * FARP * NEARP / (FARP - NEARP);

    for (int i = 0; i < 4; i++)
        for (int j = 0; j < 4; j++) {
            float sij = 0.f;
            for (int k = 0; k < 4; k++) sij += Vw[i * 4 + k] * P[k * 4 + j];
            MVP[i * 4 + j] = sij;
        }
}

// Balanced-partition fused renderer: 296 blocks (2/SM exactly), each owns a
// contiguous 55-56 pixel range (may span one row boundary). Per-piece precise
// bbox compaction; eval uses 64B records with precomputed deltas whose values
// are bit-identical to the reference's edge-function subtractions.
extern "C" __global__ void __launch_bounds__(THREADS, 2)
render_kernel(const float* __restrict__ v,
              const float* __restrict__ vc,
              const int*   __restrict__ f,
              const float* __restrict__ bg,
              const float* __restrict__ cf,
              const float* __restrict__ cc,
              const float* __restrict__ ct,
              const float* __restrict__ crt,
              float* __restrict__ out,
              int Vn, int Fn) {
    extern __shared__ char smem_raw[];
    float4*   s_t0  = (float4*)smem_raw;                              // Ax,Ay,Bx,By
    float4*   s_t1  = (float4*)((char*)s_t0 + (size_t)Fn * 16);       // Cx,Cy,dCBx,dCBy
    float4*   s_t2  = (float4*)((char*)s_t1 + (size_t)Fn * 16);       // dACx,dACy,dBAx,dBAy
    float4*   s_t3  = (float4*)((char*)s_t2 + (size_t)Fn * 16);       // za,zb,zc,inva
    unsigned* s_bbq = (unsigned*)((char*)s_t3 + (size_t)Fn * 16);     // u8x4 bbox
    float4*   s_vert = (float4*)((char*)s_bbq + (size_t)Fn * 4);      // Vn
    unsigned long long* s_red =
        (unsigned long long*)((char*)s_vert + (size_t)Vn * 16);       // SLICES*MAXPXB
    int* s_list = (int*)((char*)s_red + (size_t)SLICES * MAXPXB * 8); // Fn
    __shared__ float MVP[16];
    __shared__ int s_cnt;

    int tid = threadIdx.x;
    int b   = blockIdx.y;

    if (tid == 0) { compute_mvp(cf, cc, ct, crt, MVP); s_cnt = 0; }
    __syncthreads();

    // ---- vertex transform (validity folded into sign of .w) ----
    for (int i = tid; i < Vn; i += THREADS) {
        const float* vp = v + ((size_t)b * Vn + i) * 3;
        float X = vp[0], Y = vp[1], Z = vp[2];
        float c0 = X * MVP[0] + Y * MVP[4] + Z * MVP[8]  + MVP[12];
        float c1 = X * MVP[1] + Y * MVP[5] + Z * MVP[9]  + MVP[13];
        float c2 = X * MVP[2] + Y * MVP[6] + Z * MVP[10] + MVP[14];
        float c3 = X * MVP[3] + Y * MVP[7] + Z * MVP[11] + MVP[15];
        bool valid = c3 > EPSV;
        float ws = valid ? c3 : 1.f;
        float nx = c0 / ws, ny = c1 / ws, nz = c2 / ws;
        float xs = (nx * 0.5f + 0.5f) * (float)WIDTH;
        float ys = (0.5f - ny * 0.5f) * (float)HEIGHT;
        float iw = 1.f / ws;
        s_vert[i] = make_float4(xs, ys, nz, valid ? iw : -1.f);
    }
    __syncthreads();

    // ---- triangle setup: 64B record + conservative quantized bbox ----
    for (int t = tid; t < Fn; t += THREADS) {
        int i0 = f[t * 3 + 0], i1 = f[t * 3 + 1], i2 = f[t * 3 + 2];
        float4 A  = s_vert[i0];
        float4 Bv = s_vert[i1];
        float4 C  = s_vert[i2];
        float area = (Bv.x - A.x) * (C.y - A.y) - (Bv.y - A.y) * (C.x - A.x);
        bool va = fabsf(area) > EPSV;
        float area_safe = va ? area : 1.f;
        float inva = 1.f / area_safe;
        bool valid = (A.w > 0.f) && (Bv.w > 0.f) && (C.w > 0.f) && va;
        float za = A.z, zb = Bv.z, zc = C.z;
        if (!valid) {
            float qn = __int_as_float(0x7FC00000);   // NaN -> never selected
            za = qn; zb = qn; zc = qn;
        }
        int xmn = __float2int_rd(fminf(A.x, fminf(Bv.x, C.x)));
        int xmx = __float2int_ru(fmaxf(A.x, fmaxf(Bv.x, C.x)));
        int ymn = __float2int_rd(fminf(A.y, fminf(Bv.y, C.y)));
        int ymx = __float2int_ru(fmaxf(A.y, fmaxf(Bv.y, C.y)));
        xmn = min(max(xmn, 0), 255); xmx = min(max(xmx, 0), 255);
        ymn = min(max(ymn, 0), 255); ymx = min(max(ymx, 0), 255);
        s_bbq[t] = (unsigned)xmn | ((unsigned)xmx << 8) |
                   ((unsigned)ymn << 16) | ((unsigned)ymx << 24);
        s_t0[t] = make_float4(A.x, A.y, Bv.x, Bv.y);
        s_t1[t] = make_float4(C.x, C.y, C.x - Bv.x, C.y - Bv.y);
        s_t2[t] = make_float4(A.x - C.x, A.y - C.y, Bv.x - A.x, Bv.y - A.y);
        s_t3[t] = make_float4(za, zb, zc, inva);
    }
    __syncthreads();

    // ---- this block's pixel range [p0, p1), may span one row boundary ----
    int p0  = (int)(((long long)blockIdx.x * NPX) / GRIDX);
    int p1  = (int)(((long long)(blockIdx.x + 1) * NPX) / GRIDX);
    int cnt = p1 - p0;                         // 55 or 56

    int rowA = p0 >> 7;                        // first row
    int rowB = (p1 - 1) >> 7;                  // last row (rowA or rowA+1)
    // piece A: row rowA, x in [xAlo, xAhi]; piece B (if spanning): row rowB, x in [0, xBhi]
    int xAlo = p0 & (WIDTH - 1);
    int xAhi = (rowB == rowA) ? ((p1 - 1) & (WIDTH - 1)) : (WIDTH - 1);
    int xBhi = (p1 - 1) & (WIDTH - 1);
    bool twoRows = (rowB != rowA);

    // ---- precise per-piece bbox compaction ----
    for (int t = tid; t < Fn; t += THREADS) {
        unsigned q = s_bbq[t];
        int xmn = q & 255, xmx = (q >> 8) & 255;
        int ymn = (q >> 16) & 255, ymx = q >> 24;
        bool hitA = (ymn <= rowA) && (ymx > rowA) && (xmn <= xAhi) && (xmx > xAlo);
        bool hitB = twoRows && (ymn <= rowB) && (ymx > rowB) && (xmn <= xBhi);
        if (hitA || hitB) {
            int slot = atomicAdd(&s_cnt, 1);   // unordered ok: key-min is order-invariant
            s_list[slot] = t;
        }
    }
    __syncthreads();
    int n = s_cnt;

    // ---- balanced eval: warp = slice, lane = pixel pair (p0+lane, p0+lane+32) ----
    int lane  = tid & 31;
    int slice = tid >> 5;
    int pA = p0 + lane;                        // always < p1 (cnt >= 55 > 32)
    int pB = p0 + lane + 32;
    bool validB = (lane + 32) < cnt;
    float yA = (float)(pA >> 7) + 0.5f;
    float xA = (float)(pA & (WIDTH - 1)) + 0.5f;
    float yB = (float)(pB >> 7) + 0.5f;
    float xB = (float)(pB & (WIDTH - 1)) + 0.5f;

    float bzA = INFINITY, bzB = INFINITY;
    int   biA = -1,       biB = -1;

#pragma unroll 2
    for (int i = slice; i < n; i += SLICES) {
        int t = s_list[i];                // warp-uniform broadcast
        float4 T0 = s_t0[i >= 0 ? t : 0];
        float4 T1 = s_t1[t];
        float4 T2 = s_t2[t];
        float4 T3 = s_t3[t];
        float inva = T3.w;

        {   // pixel A
            float w0 = T1.z * (yA - T0.w) - T1.w * (xA - T0.z);
            float w1 = T2.x * (yA - T1.y) - T2.y * (xA - T1.x);
            float w2 = T2.z * (yA - T0.y) - T2.w * (xA - T0.x);
            float b0 = w0 * inva, b1 = w1 * inva, b2 = w2 * inva;
            float z = b0 * T3.x + b1 * T3.y + b2 * T3.z;   // NaN if invalid
            bool inside = (b0 >= 0.f) && (b1 >= 0.f) && (b2 >= 0.f) &&
                          (z >= -1.f) && (z <= 1.f);
            if (inside && z < bzA) { bzA = z; biA = t; }
        }
        {   // pixel B
            float w0 = T1.z * (yB - T0.w) - T1.w * (xB - T0.z);
            float w1 = T2.x * (yB - T1.y) - T2.y * (xB - T1.x);
            float w2 = T2.z * (yB - T0.y) - T2.w * (xB - T0.x);
            float b0 = w0 * inva, b1 = w1 * inva, b2 = w2 * inva;
            float z = b0 * T3.x + b1 * T3.y + b2 * T3.z;
            bool inside = (b0 >= 0.f) && (b1 >= 0.f) && (b2 >= 0.f) &&
                          (z >= -1.f) && (z <= 1.f);
            if (inside && z < bzB) { bzB = z; biB = t; }
        }
    }

    // pack (orderable z, tri idx): lexicographic min == argmin first-index
    unsigned long long kA = ~0ull, kB = ~0ull;
    if (biA >= 0) {
        unsigned zu = __float_as_uint(bzA);
        zu = (zu & 0x80000000u) ? ~zu : (zu | 0x80000000u);
        kA = ((unsigned long long)zu << 32) | (unsigned)biA;
    }
    if (biB >= 0 && validB) {
        unsigned zu = __float_as_uint(bzB);
        zu = (zu & 0x80000000u) ? ~zu : (zu | 0x80000000u);
        kB = ((unsigned long long)zu << 32) | (unsigned)biB;
    }
    s_red[slice * MAXPXB + lane]      = kA;
    s_red[slice * MAXPXB + lane + 32] = kB;
    __syncthreads();

    // ---- merge + shade (first cnt threads) ----
    if (tid < cnt) {
        int p = tid;
        unsigned long long best = s_red[p];
#pragma unroll
        for (int sl = 1; sl < SLICES; sl++)
            best = min(best, s_red[sl * MAXPXB + p]);

        int pg = p0 + p;
        float xp = (float)(pg & (WIDTH - 1)) + 0.5f;
        float yp = (float)(pg >> 7) + 0.5f;
        float cr, cg, cb;
        if ((unsigned)(best >> 32) == 0xFFFFFFFFu) {
            cr = bg[0]; cg = bg[1]; cb = bg[2];
        } else {
            int tt = (int)(unsigned)best;
            float4 T0 = s_t0[tt];
            float4 T1 = s_t1[tt];
            float4 T2 = s_t2[tt];
            float4 T3 = s_t3[tt];
            float w0 = T1.z * (yp - T0.w) - T1.w * (xp - T0.z);
            float w1 = T2.x * (yp - T1.y) - T2.y * (xp - T1.x);
            float w2 = T2.z * (yp - T0.y) - T2.w * (xp - T0.x);
            float inva = T3.w;
            float b0 = w0 * inva, b1 = w1 * inva, b2 = w2 * inva;
            int i0 = f[tt * 3 + 0], i1 = f[tt * 3 + 1], i2 = f[tt * 3 + 2];
            float q0 = b0 * s_vert[i0].w;   // selected => all verts valid => +invw
            float q1 = b1 * s_vert[i1].w;
            float q2 = b2 * s_vert[i2].w;
            float den = q0 + q1 + q2;
            if (!(fabsf(den) > EPSV)) den = 1.f;
            cr = (q0 * vc[i0 * 3 + 0] + q1 * vc[i1 * 3 + 0] + q2 * vc[i2 * 3 + 0]) / den;
            cg = (q0 * vc[i0 * 3 + 1] + q1 * vc[i1 * 3 + 1] + q2 * vc[i2 * 3 + 1]) / den;
            cb = (q0 * vc[i0 * 3 + 2] + q1 * vc[i1 * 3 + 2] + q2 * vc[i2 * 3 + 2]) / den;
        }
        float* op = out + ((size_t)b * NPX + pg) * 3;
        op[0] = cr; op[1] = cg; op[2] = cb;
    }
}

extern "C" void kernel_launch(void* const* d_in, const int* in_sizes, int n_in,
                              void* d_out, int out_size) {
    const float* v   = (const float*)d_in[0];
    const float* vc  = (const float*)d_in[1];
    const int*   f   = (const int*)d_in[2];
    const float* bg  = (const float*)d_in[3];
    const float* cf  = (const float*)d_in[4];
    const float* cc  = (const float*)d_in[5];
    const float* ct  = (const float*)d_in[6];
    const float* crt = (const float*)d_in[7];

    int Vn = in_sizes[1] / 3;
    int Fn = in_sizes[2] / 3;
    int Bn = in_sizes[0] / (3 * Vn);

    size_t smem = (size_t)Fn * 64 + (size_t)Fn * 4 + (size_t)Vn * 16 +
                  (size_t)SLICES * MAXPXB * 8 + (size_t)Fn * 4;
    static int smem_set = 0;
    if (!smem_set) {
        cudaFuncSetAttribute(render_kernel,
                             cudaFuncAttributeMaxDynamicSharedMemorySize,
                             (int)smem);
        smem_set = 1;
    }
    dim3 grid(GRIDX, Bn);
    render_kernel<<<grid, THREADS, smem>>>(v, vc, f, bg, cf, cc, ct, crt,
                                           (float*)d_out, Vn, Fn);
}

// round 13
// speedup vs baseline: 1.2772x; 1.1105x over previous
#include <cuda_runtime.h>
#include <math.h>

#define WIDTH  128
#define HEIGHT 128
#define NPX    (WIDTH * HEIGHT)
#define NEARP  0.1f
#define FARP   10.0f
#define EPSV   1e-8f

#define THREADS   512
#define TILE      8      // 8x8 pixel tile per block
#define TILES_X   (WIDTH / TILE)     // 16
#define PX_TILE   (TILE * TILE)      // 64 pixels per block
#define SLICES    16     // warps per block

__device__ __forceinline__ void compute_mvp(const float* cf, const float* cc,
                                            const float* tt, const float* rt,
                                            float* MVP) {
    float r0 = rt[0], r1 = rt[1], r2 = rt[2];
    float theta = sqrtf(r0 * r0 + r1 * r1 + r2 * r2 + 1e-12f);
    float k0 = r0 / theta, k1 = r1 / theta, k2 = r2 / theta;
    float st = sinf(theta), ctv = cosf(theta);
    float K[9] = { 0.f, -k2,  k1,
                   k2,  0.f, -k0,
                  -k1,  k0,  0.f };
    float KK[9];
    for (int i = 0; i < 3; i++)
        for (int j = 0; j < 3; j++) {
            float s = 0.f;
            for (int k = 0; k < 3; k++) s += K[i * 3 + k] * K[k * 3 + j];
            KK[i * 3 + j] = s;
        }
    float R[9];
    for (int i = 0; i < 3; i++)
        for (int j = 0; j < 3; j++)
            R[i * 3 + j] = (i == j ? 1.f : 0.f) + st * K[i * 3 + j] + (1.f - ctv) * KK[i * 3 + j];

    float Vw[16];
    for (int i = 0; i < 3; i++) {
        for (int j = 0; j < 3; j++) Vw[i * 4 + j] = R[j * 3 + i];
        Vw[i * 4 + 3] = 0.f;
    }
    Vw[12] = tt[0]; Vw[13] = tt[1]; Vw[14] = tt[2]; Vw[15] = 1.f;

    float fav = 0.5f * (cf[0] + cf[1]);
    float s = NEARP / fav;
    float right  = ((float)WIDTH - (cc[0] + 0.5f)) * s;
    float left   = -(cc[0] + 0.5f) * s;
    float top    = (cc[1] + 0.5f) * s;
    float bottom = -((float)HEIGHT - cc[1] + 0.5f) * s;
    float P[16];
    for (int i = 0; i < 16; i++) P[i] = 0.f;
    P[0]  = 2.f * NEARP / (right - left);
    P[5]  = 2.f * NEARP / (top - bottom);
    P[8]  = (right + left) / (right - left);
    P[9]  = (top + bottom) / (top - bottom);
    P[10] = -(FARP + NEARP) / (FARP - NEARP);
    P[11] = -1.f;
    P[14] = -2.f * FARP * NEARP / (FARP - NEARP);

    for (int i = 0; i < 4; i++)
        for (int j = 0; j < 4; j++) {
            float sij = 0.f;
            for (int k = 0; k < 4; k++) sij += Vw[i * 4 + k] * P[k * 4 + j];
            MVP[i * 4 + j] = sij;
        }
}

// Fused renderer, 8x8-tile blocks: setup -> quantized-bbox compaction against
// the tile's x AND y windows (tight 2D culling) -> balanced eval over
// survivors -> (z,idx)-key argmin merge -> shade.
// Eval arithmetic identical to the proven R6 kernel.
extern "C" __global__ void __launch_bounds__(THREADS, 2)
render_kernel(const float* __restrict__ v,
              const float* __restrict__ vc,
              const int*   __restrict__ f,
              const float* __restrict__ bg,
              const float* __restrict__ cf,
              const float* __restrict__ cc,
              const float* __restrict__ ct,
              const float* __restrict__ crt,
              float* __restrict__ out,
              int Vn, int Fn) {
    extern __shared__ char smem_raw[];
    float4*   s_triA = (float4*)smem_raw;                             // Fn: Ax,Ay,Bx,By
    float4*   s_triB = (float4*)((char*)s_triA + (size_t)Fn * 16);    // Fn: Cx,Cy,za,zb
    float2*   s_triC = (float2*)((char*)s_triB + (size_t)Fn * 16);    // Fn: zc,inva
    unsigned* s_bbq  = (unsigned*)((char*)s_triC + (size_t)Fn * 8);   // Fn: u8x4 bbox
    float4*   s_vert = (float4*)((char*)s_bbq + (size_t)Fn * 4);      // Vn
    unsigned long long* s_red =
        (unsigned long long*)((char*)s_vert + (size_t)Vn * 16);       // SLICES*PX_TILE
    int* s_list = (int*)((char*)s_red + (size_t)SLICES * PX_TILE * 8);// Fn
    __shared__ float MVP[16];
    __shared__ int s_cnt;

    int tid = threadIdx.x;
    int b   = blockIdx.y;

    if (tid == 0) { compute_mvp(cf, cc, ct, crt, MVP); s_cnt = 0; }
    __syncthreads();

    // ---- vertex transform (validity folded into sign of .w) ----
    for (int i = tid; i < Vn; i += THREADS) {
        const float* vp = v + ((size_t)b * Vn + i) * 3;
        float X = vp[0], Y = vp[1], Z = vp[2];
        float c0 = X * MVP[0] + Y * MVP[4] + Z * MVP[8]  + MVP[12];
        float c1 = X * MVP[1] + Y * MVP[5] + Z * MVP[9]  + MVP[13];
        float c2 = X * MVP[2] + Y * MVP[6] + Z * MVP[10] + MVP[14];
        float c3 = X * MVP[3] + Y * MVP[7] + Z * MVP[11] + MVP[15];
        bool valid = c3 > EPSV;
        float ws = valid ? c3 : 1.f;
        float nx = c0 / ws, ny = c1 / ws, nz = c2 / ws;
        float xs = (nx * 0.5f + 0.5f) * (float)WIDTH;
        float ys = (0.5f - ny * 0.5f) * (float)HEIGHT;
        float iw = 1.f / ws;
        s_vert[i] = make_float4(xs, ys, nz, valid ? iw : -1.f);
    }
    __syncthreads();

    // ---- triangle setup (40B record) + conservative quantized bbox ----
    for (int t = tid; t < Fn; t += THREADS) {
        int i0 = f[t * 3 + 0], i1 = f[t * 3 + 1], i2 = f[t * 3 + 2];
        float4 A  = s_vert[i0];
        float4 Bv = s_vert[i1];
        float4 C  = s_vert[i2];
        float area = (Bv.x - A.x) * (C.y - A.y) - (Bv.y - A.y) * (C.x - A.x);
        bool va = fabsf(area) > EPSV;
        float area_safe = va ? area : 1.f;
        float inva = 1.f / area_safe;
        bool valid = (A.w > 0.f) && (Bv.w > 0.f) && (C.w > 0.f) && va;
        float za = A.z, zb = Bv.z, zc = C.z;
        if (!valid) {
            float qn = __int_as_float(0x7FC00000);   // NaN -> never selected
            za = qn; zb = qn; zc = qn;
        }
        int xmn = __float2int_rd(fminf(A.x, fminf(Bv.x, C.x)));
        int xmx = __float2int_ru(fmaxf(A.x, fmaxf(Bv.x, C.x)));
        int ymn = __float2int_rd(fminf(A.y, fminf(Bv.y, C.y)));
        int ymx = __float2int_ru(fmaxf(A.y, fmaxf(Bv.y, C.y)));
        xmn = min(max(xmn, 0), 255); xmx = min(max(xmx, 0), 255);
        ymn = min(max(ymn, 0), 255); ymx = min(max(ymx, 0), 255);
        s_bbq[t]  = (unsigned)xmn | ((unsigned)xmx << 8) |
                    ((unsigned)ymn << 16) | ((unsigned)ymx << 24);
        s_triA[t] = make_float4(A.x, A.y, Bv.x, Bv.y);
        s_triB[t] = make_float4(C.x, C.y, za, zb);
        s_triC[t] = make_float2(zc, inva);
    }
    __syncthreads();

    // ---- tile window & 2D bbox compaction ----
    int tileX = blockIdx.x & (TILES_X - 1);
    int tileY = blockIdx.x >> 4;            // TILES_X == 16
    int xlo_i = tileX * TILE, xhi_i = xlo_i + (TILE - 1);
    int ylo_i = tileY * TILE, yhi_i = ylo_i + (TILE - 1);

    for (int t = tid; t < Fn; t += THREADS) {
        unsigned q = s_bbq[t];
        int xmn = q & 255, xmx = (q >> 8) & 255;
        int ymn = (q >> 16) & 255, ymx = q >> 24;
        bool hit = (ymn <= yhi_i) && (ymx > ylo_i) &&
                   (xmn <= xhi_i) && (xmx > xlo_i);
        if (hit) {
            int slot = atomicAdd(&s_cnt, 1);   // unordered ok: key-min is order-invariant
            s_list[slot] = t;
        }
    }
    __syncthreads();
    int n = s_cnt;

    // ---- balanced eval: warp = slice, lane owns 2 tile pixels (p, p+32) ----
    int lane  = tid & 31;
    int slice = tid >> 5;
    int pA = lane, pB = lane + 32;
    float xA = (float)(xlo_i + (pA & (TILE - 1))) + 0.5f;
    float yA = (float)(ylo_i + (pA >> 3)) + 0.5f;        // TILE == 8
    float xB = (float)(xlo_i + (pB & (TILE - 1))) + 0.5f;
    float yB = (float)(ylo_i + (pB >> 3)) + 0.5f;

    float bzA = INFINITY, bzB = INFINITY;
    int   biA = -1,       biB = -1;

#pragma unroll 2
    for (int i = slice; i < n; i += SLICES) {
        int t = s_list[i];                // warp-uniform broadcast
        float4 TA = s_triA[t];            // Ax,Ay,Bx,By
        float4 TB = s_triB[t];            // Cx,Cy,za,zb
        float2 TC = s_triC[t];            // zc,inva
        float dCBx = TB.x - TA.z, dCBy = TB.y - TA.w;
        float dACx = TA.x - TB.x, dACy = TA.y - TB.y;
        float dBAx = TA.z - TA.x, dBAy = TA.w - TA.y;
        float inva = TC.y;

        {   // pixel A
            float w0 = dCBx * (yA - TA.w) - dCBy * (xA - TA.z);
            float w1 = dACx * (yA - TB.y) - dACy * (xA - TB.x);
            float w2 = dBAx * (yA - TA.y) - dBAy * (xA - TA.x);
            float b0 = w0 * inva, b1 = w1 * inva, b2 = w2 * inva;
            float z = b0 * TB.z + b1 * TB.w + b2 * TC.x;   // NaN if invalid
            bool inside = (b0 >= 0.f) && (b1 >= 0.f) && (b2 >= 0.f) &&
                          (z >= -1.f) && (z <= 1.f);
            if (inside && z < bzA) { bzA = z; biA = t; }
        }
        {   // pixel B
            float w0 = dCBx * (yB - TA.w) - dCBy * (xB - TA.z);
            float w1 = dACx * (yB - TB.y) - dACy * (xB - TB.x);
            float w2 = dBAx * (yB - TA.y) - dBAy * (xB - TA.x);
            float b0 = w0 * inva, b1 = w1 * inva, b2 = w2 * inva;
            float z = b0 * TB.z + b1 * TB.w + b2 * TC.x;
            bool inside = (b0 >= 0.f) && (b1 >= 0.f) && (b2 >= 0.f) &&
                          (z >= -1.f) && (z <= 1.f);
            if (inside && z < bzB) { bzB = z; biB = t; }
        }
    }

    // pack (orderable z, tri idx): lexicographic min == argmin first-index
    unsigned long long kA = ~0ull, kB = ~0ull;
    if (biA >= 0) {
        unsigned zu = __float_as_uint(bzA);
        zu = (zu & 0x80000000u) ? ~zu : (zu | 0x80000000u);
        kA = ((unsigned long long)zu << 32) | (unsigned)biA;
    }
    if (biB >= 0) {
        unsigned zu = __float_as_uint(bzB);
        zu = (zu & 0x80000000u) ? ~zu : (zu | 0x80000000u);
        kB = ((unsigned long long)zu << 32) | (unsigned)biB;
    }
    s_red[slice * PX_TILE + pA] = kA;
    s_red[slice * PX_TILE + pB] = kB;
    __syncthreads();

    // ---- merge + shade (first PX_TILE threads) ----
    if (tid < PX_TILE) {
        int p = tid;
        unsigned long long best = s_red[p];
#pragma unroll
        for (int sl = 1; sl < SLICES; sl++)
            best = min(best, s_red[sl * PX_TILE + p]);

        int gx = xlo_i + (p & (TILE - 1));
        int gy = ylo_i + (p >> 3);
        float xp = (float)gx + 0.5f;
        float yp = (float)gy + 0.5f;
        float cr, cg, cb;
        if ((unsigned)(best >> 32) == 0xFFFFFFFFu) {
            cr = bg[0]; cg = bg[1]; cb = bg[2];
        } else {
            int tt = (int)(unsigned)best;
            float4 TA = s_triA[tt];
            float4 TB = s_triB[tt];
            float2 TC = s_triC[tt];
            float dCBx = TB.x - TA.z, dCBy = TB.y - TA.w;
            float dACx = TA.x - TB.x, dACy = TA.y - TB.y;
            float dBAx = TA.z - TA.x, dBAy = TA.w - TA.y;
            float w0 = dCBx * (yp - TA.w) - dCBy * (xp - TA.z);
            float w1 = dACx * (yp - TB.y) - dACy * (xp - TB.x);
            float w2 = dBAx * (yp - TA.y) - dBAy * (xp - TA.x);
            float inva = TC.y;
            float b0 = w0 * inva, b1 = w1 * inva, b2 = w2 * inva;
            int i0 = f[tt * 3 + 0], i1 = f[tt * 3 + 1], i2 = f[tt * 3 + 2];
            float q0 = b0 * s_vert[i0].w;   // selected => all verts valid => +invw
            float q1 = b1 * s_vert[i1].w;
            float q2 = b2 * s_vert[i2].w;
            float den = q0 + q1 + q2;
            if (!(fabsf(den) > EPSV)) den = 1.f;
            cr = (q0 * vc[i0 * 3 + 0] + q1 * vc[i1 * 3 + 0] + q2 * vc[i2 * 3 + 0]) / den;
            cg = (q0 * vc[i0 * 3 + 1] + q1 * vc[i1 * 3 + 1] + q2 * vc[i2 * 3 + 1]) / den;
            cb = (q0 * vc[i0 * 3 + 2] + q1 * vc[i1 * 3 + 2] + q2 * vc[i2 * 3 + 2]) / den;
        }
        float* op = out + ((size_t)b * NPX + (size_t)gy * WIDTH + gx) * 3;
        op[0] = cr; op[1] = cg; op[2] = cb;
    }
}

extern "C" void kernel_launch(void* const* d_in, const int* in_sizes, int n_in,
                              void* d_out, int out_size) {
    const float* v   = (const float*)d_in[0];
    const float* vc  = (const float*)d_in[1];
    const int*   f   = (const int*)d_in[2];
    const float* bg  = (const float*)d_in[3];
    const float* cf  = (const float*)d_in[4];
    const float* cc  = (const float*)d_in[5];
    const float* ct  = (const float*)d_in[6];
    const float* crt = (const float*)d_in[7];

    int Vn = in_sizes[1] / 3;
    int Fn = in_sizes[2] / 3;
    int Bn = in_sizes[0] / (3 * Vn);

    size_t smem = (size_t)Fn * 44 + (size_t)Vn * 16 +
                  (size_t)SLICES * PX_TILE * 8 + (size_t)Fn * 4;
    static int smem_set = 0;
    if (!smem_set) {
        cudaFuncSetAttribute(render_kernel,
                             cudaFuncAttributeMaxDynamicSharedMemorySize,
                             (int)smem);
        smem_set = 1;
    }
    dim3 grid((WIDTH / TILE) * (HEIGHT / TILE), Bn);
    render_kernel<<<grid, THREADS, smem>>>(v, vc, f, bg, cf, cc, ct, crt,
                                           (float*)d_out, Vn, Fn);
}